// round 1
// baseline (speedup 1.0000x reference)
#include <cuda_runtime.h>
#include <cstdint>

// Problem constants
#define BATCH   64
#define NNODE   5000
#define CIN     64
#define COUT    64
#define DDIM    10
// per-batch plane stride in x / y / out
#define PLANE   (NNODE * CIN)       // 320000

// Scratch in device globals (no allocations allowed)
__device__ float g_support[NNODE * NNODE];     // 100 MB: softmax(relu(E E^T))
__device__ float g_y[BATCH * NNODE * CIN];     // 82 MB: support @ x

// ---------------------------------------------------------------------------
// Kernel 1: support[n,m] = softmax_m( relu( E[n,:] . E[m,:] ) )
// One block per row n, 256 threads, up to 20 columns per thread in registers.
// ---------------------------------------------------------------------------
__global__ __launch_bounds__(256)
void support_kernel(const float* __restrict__ E)
{
    const int n   = blockIdx.x;
    const int tid = threadIdx.x;

    __shared__ float e_n[DDIM];
    __shared__ float red[256];

    if (tid < DDIM) e_n[tid] = E[n * DDIM + tid];
    __syncthreads();

    float v[20];
    float mx = -1e30f;
    #pragma unroll
    for (int j = 0; j < 20; ++j) {
        int m = j * 256 + tid;
        float dot = 0.0f;
        if (m < NNODE) {
            const float* em = E + m * DDIM;
            #pragma unroll
            for (int d = 0; d < DDIM; ++d) dot += e_n[d] * em[d];
            dot = fmaxf(dot, 0.0f);
            v[j] = dot;
            mx = fmaxf(mx, dot);
        } else {
            v[j] = -1e30f;
        }
    }

    // block max
    red[tid] = mx; __syncthreads();
    for (int s = 128; s > 0; s >>= 1) {
        if (tid < s) red[tid] = fmaxf(red[tid], red[tid + s]);
        __syncthreads();
    }
    mx = red[0];
    __syncthreads();

    // exp + block sum
    float sum = 0.0f;
    #pragma unroll
    for (int j = 0; j < 20; ++j) {
        int m = j * 256 + tid;
        if (m < NNODE) {
            v[j] = __expf(v[j] - mx);
            sum += v[j];
        }
    }
    red[tid] = sum; __syncthreads();
    for (int s = 128; s > 0; s >>= 1) {
        if (tid < s) red[tid] += red[tid + s];
        __syncthreads();
    }
    float inv = 1.0f / red[0];

    float* srow = g_support + (size_t)n * NNODE;
    #pragma unroll
    for (int j = 0; j < 20; ++j) {
        int m = j * 256 + tid;
        if (m < NNODE) srow[m] = v[j] * inv;
    }
}

// ---------------------------------------------------------------------------
// Kernel 2: y[b,n,c] = sum_m support[n,m] * x[b,m,c]
// Treated as SGEMM: A = support (5000x5000), Bmat = x viewed as (5000 x 4096)
// with column index col = b*64 + c (b-stride = PLANE).
// Tiling: BM=128, BN=128, BK=8, 256 threads, 8x8 per-thread microtile.
// Grid: x = col tile (fastest -> same A row-panel is L2-resident), y = row tile.
// ---------------------------------------------------------------------------
#define BM 128
#define BN 128
#define BK 8
#define TM 8
#define TN 8

__global__ __launch_bounds__(256)
void spmm_kernel(const float* __restrict__ X)
{
    const int colBase = blockIdx.x * BN;   // 0..4095
    const int rowBase = blockIdx.y * BM;   // 0..5119 (last tile partial)

    __shared__ float As[BK][BM + 4];
    __shared__ float Bs[BK][BN];

    const int tid  = threadIdx.x;
    const int tcol = tid & 15;    // 0..15
    const int trow = tid >> 4;    // 0..15

    // A-load mapping: thread -> (row = tid/2, kk = (tid&1)*4), float4 along k
    const int aRow = tid >> 1;
    const int aK   = (tid & 1) * 4;
    // B-load mapping: thread -> (kk = tid/32, col = (tid&31)*4), float4 along c
    const int bK   = tid >> 5;
    const int bCol = (tid & 31) * 4;
    const int gcol = colBase + bCol;
    const int gb   = gcol >> 6;
    const int gc   = gcol & 63;
    const float* Xb = X + (size_t)gb * PLANE + gc;

    const int aGRow = rowBase + aRow;
    const float* Arow = g_support + (size_t)aGRow * NNODE;
    const bool aValid = (aGRow < NNODE);

    float acc[TM][TN];
    #pragma unroll
    for (int i = 0; i < TM; ++i)
        #pragma unroll
        for (int j = 0; j < TN; ++j) acc[i][j] = 0.0f;

    for (int k0 = 0; k0 < NNODE; k0 += BK) {
        float4 av = make_float4(0.f, 0.f, 0.f, 0.f);
        if (aValid) av = *(const float4*)(Arow + k0 + aK);
        As[aK + 0][aRow] = av.x;
        As[aK + 1][aRow] = av.y;
        As[aK + 2][aRow] = av.z;
        As[aK + 3][aRow] = av.w;

        float4 bv = *(const float4*)(Xb + (size_t)(k0 + bK) * CIN);
        *(float4*)&Bs[bK][bCol] = bv;

        __syncthreads();

        #pragma unroll
        for (int kk = 0; kk < BK; ++kk) {
            float a[TM], b[TN];
            #pragma unroll
            for (int i = 0; i < TM; ++i) a[i] = As[kk][trow * TM + i];
            #pragma unroll
            for (int j = 0; j < TN; ++j) b[j] = Bs[kk][tcol * TN + j];
            #pragma unroll
            for (int i = 0; i < TM; ++i)
                #pragma unroll
                for (int j = 0; j < TN; ++j)
                    acc[i][j] += a[i] * b[j];
        }
        __syncthreads();
    }

    // store
    #pragma unroll
    for (int i = 0; i < TM; ++i) {
        int grow = rowBase + trow * TM + i;
        if (grow >= NNODE) continue;
        #pragma unroll
        for (int j = 0; j < TN; j += 4) {
            int col = colBase + tcol * TN + j;
            int b = col >> 6, c = col & 63;
            float4 vv = make_float4(acc[i][j], acc[i][j + 1], acc[i][j + 2], acc[i][j + 3]);
            *(float4*)(g_y + (size_t)b * PLANE + (size_t)grow * CIN + c) = vv;
        }
    }
}

// ---------------------------------------------------------------------------
// Kernel 3: per-node contraction + bias.
// W_n[ki, o] = sum_d E[n,d] * wp[d, ki, o]   (ki = k*64+i, 128x64 in smem)
// A_n[ki, b] = x[b,n,i] (ki<64) or y[b,n,i-64]  (stored transposed [ki][b])
// out[b,n,o] = sum_ki A_n[ki,b] * W_n[ki,o] + sum_d E[n,d]*bp[d,o]
// One block per node, 256 threads, 4x4 microtile over (b,o).
// Dynamic smem: 64 KB (W 32KB + A 32KB).
// ---------------------------------------------------------------------------
extern __shared__ float s_mem[];

__global__ __launch_bounds__(256)
void node_mlp_kernel(const float* __restrict__ X,
                     const float* __restrict__ E,
                     const float* __restrict__ wp,
                     const float* __restrict__ bp,
                     float* __restrict__ out)
{
    const int n   = blockIdx.x;
    const int tid = threadIdx.x;

    float* Wsh = s_mem;          // [128][64]  -> Wsh[ki*64 + o]
    float* Ash = s_mem + 8192;   // [128][64]  -> Ash[ki*64 + b]
    __shared__ float e_sh[DDIM];

    if (tid < DDIM) e_sh[tid] = E[n * DDIM + tid];
    __syncthreads();

    // Build W_n (8192 entries, 32 per thread)
    #pragma unroll
    for (int idx = tid; idx < 8192; idx += 256) {
        float s = 0.0f;
        #pragma unroll
        for (int d = 0; d < DDIM; ++d) s += e_sh[d] * wp[d * 8192 + idx];
        Wsh[idx] = s;
    }

    // Build A_n transposed: Ash[ki*64 + b]
    #pragma unroll
    for (int idx = tid; idx < 2048; idx += 256) {
        int b  = idx >> 5;
        int i4 = (idx & 31) * 4;   // 0..124
        float4 vv;
        if (i4 < 64)
            vv = *(const float4*)(X + (size_t)b * PLANE + (size_t)n * CIN + i4);
        else
            vv = *(const float4*)(g_y + (size_t)b * PLANE + (size_t)n * CIN + (i4 - 64));
        Ash[(i4 + 0) * 64 + b] = vv.x;
        Ash[(i4 + 1) * 64 + b] = vv.y;
        Ash[(i4 + 2) * 64 + b] = vv.z;
        Ash[(i4 + 3) * 64 + b] = vv.w;
    }
    __syncthreads();

    const int tb = (tid >> 4) * 4;   // b tile base 0..60
    const int to = (tid & 15) * 4;   // o tile base 0..60

    float acc[4][4];
    #pragma unroll
    for (int i = 0; i < 4; ++i)
        #pragma unroll
        for (int j = 0; j < 4; ++j) acc[i][j] = 0.0f;

    #pragma unroll 4
    for (int ki = 0; ki < 128; ++ki) {
        float4 a = *(const float4*)&Ash[ki * 64 + tb];
        float4 w = *(const float4*)&Wsh[ki * 64 + to];
        float aa[4] = {a.x, a.y, a.z, a.w};
        float ww[4] = {w.x, w.y, w.z, w.w};
        #pragma unroll
        for (int i = 0; i < 4; ++i)
            #pragma unroll
            for (int j = 0; j < 4; ++j)
                acc[i][j] += aa[i] * ww[j];
    }

    // bias for the 4 output channels of this thread
    float bias[4];
    #pragma unroll
    for (int j = 0; j < 4; ++j) {
        float s = 0.0f;
        #pragma unroll
        for (int d = 0; d < DDIM; ++d) s += e_sh[d] * bp[d * COUT + to + j];
        bias[j] = s;
    }

    #pragma unroll
    for (int i = 0; i < 4; ++i) {
        float4 vv = make_float4(acc[i][0] + bias[0], acc[i][1] + bias[1],
                                acc[i][2] + bias[2], acc[i][3] + bias[3]);
        *(float4*)(out + (size_t)(tb + i) * PLANE + (size_t)n * COUT + to) = vv;
    }
}

// ---------------------------------------------------------------------------
extern "C" void kernel_launch(void* const* d_in, const int* in_sizes, int n_in,
                              void* d_out, int out_size)
{
    const float* x  = (const float*)d_in[0];   // (64, 5000, 64)
    const float* E  = (const float*)d_in[1];   // (5000, 10)
    const float* wp = (const float*)d_in[2];   // (10, 2, 64, 64)
    const float* bp = (const float*)d_in[3];   // (10, 64)
    float* out = (float*)d_out;                // (64, 5000, 64)

    // 1) adaptive adjacency with row softmax
    support_kernel<<<NNODE, 256>>>(E);

    // 2) y = support @ x   (batched as one wide GEMM, 4096 columns)
    dim3 grid2((BATCH * CIN) / BN, (NNODE + BM - 1) / BM);
    spmm_kernel<<<grid2, 256>>>(x);

    // 3) per-node contraction + bias
    static bool attr_done = false;  // attribute set is idempotent; safe each call too
    cudaFuncSetAttribute(node_mlp_kernel,
                         cudaFuncAttributeMaxDynamicSharedMemorySize, 65536);
    (void)attr_done;
    node_mlp_kernel<<<NNODE, 256, 65536>>>(x, E, wp, bp, out);
}

// round 3
// speedup vs baseline: 2.2702x; 2.2702x over previous
#include <cuda_runtime.h>
#include <cuda_bf16.h>
#include <cstdint>

// Problem constants
#define BATCH   64
#define NNODE   5000
#define CIN     64
#define COUT    64
#define DDIM    10
#define PLANE   (NNODE * CIN)       // 320000
#define NCOLS   (BATCH * CIN)       // 4096 GEMM output columns

// Padded GEMM dims
#define KPAD    5056                // 158 * 32
#define MPAD    5120                // 40 * 128

// GEMM tiling
#define BM      128
#define BN      128
#define BKC     32
#define NKCH    (KPAD / BKC)        // 158
#define STAGES  3

#define APITCH  80                  // bytes per smem row (64B payload + 16B pad)
#define TILE_B  (128 * APITCH)      // 10240 B per tile
#define STAGE_B (4 * TILE_B)        // Ah, Al, Bh, Bl
#define GEMM_SMEM (STAGES * STAGE_B)  // 122880 B

// ---------------------------------------------------------------------------
// Device-global scratch (no allocations allowed)
// ---------------------------------------------------------------------------
__device__ __align__(256) __nv_bfloat16 g_Ahi[(size_t)MPAD * KPAD];
__device__ __align__(256) __nv_bfloat16 g_Alo[(size_t)MPAD * KPAD];
__device__ __align__(256) __nv_bfloat16 g_Bhi[(size_t)NCOLS * KPAD];
__device__ __align__(256) __nv_bfloat16 g_Blo[(size_t)NCOLS * KPAD];
__device__ __align__(256) float         g_y[(size_t)BATCH * PLANE];

// ---------------------------------------------------------------------------
__device__ __forceinline__ uint32_t smem_u32(const void* p) {
    uint32_t a;
    asm("{ .reg .u64 t; cvta.to.shared.u64 t, %1; cvt.u32.u64 %0, t; }"
        : "=r"(a) : "l"(p));
    return a;
}

#define LDSM4(r0, r1, r2, r3, addr) \
    asm volatile("ldmatrix.sync.aligned.m8n8.x4.shared.b16 {%0,%1,%2,%3}, [%4];" \
                 : "=r"(r0), "=r"(r1), "=r"(r2), "=r"(r3) : "r"(addr))

#define MMA16816(d, a, b0, b1) \
    asm volatile("mma.sync.aligned.m16n8k16.row.col.f32.bf16.bf16.f32 " \
                 "{%0,%1,%2,%3}, {%4,%5,%6,%7}, {%8,%9}, {%0,%1,%2,%3};" \
                 : "+f"((d)[0]), "+f"((d)[1]), "+f"((d)[2]), "+f"((d)[3]) \
                 : "r"((a)[0]), "r"((a)[1]), "r"((a)[2]), "r"((a)[3]), \
                   "r"(b0), "r"(b1))

#define CPASYNC16(saddr, gaddr) \
    asm volatile("cp.async.cg.shared.global [%0], [%1], 16;" \
                 :: "r"(saddr), "l"(gaddr))

// ---------------------------------------------------------------------------
// Kernel 1: softmax(relu(E E^T)) row -> bf16 hi/lo, padded rows into g_Ahi/lo.
// ---------------------------------------------------------------------------
__global__ __launch_bounds__(256)
void support_split_kernel(const float* __restrict__ E)
{
    const int n   = blockIdx.x;
    const int tid = threadIdx.x;
    __nv_bfloat16* rh = g_Ahi + (size_t)n * KPAD;
    __nv_bfloat16* rl = g_Alo + (size_t)n * KPAD;

    if (n >= NNODE) {
        const __nv_bfloat16 z = __float2bfloat16(0.0f);
        for (int m = tid; m < KPAD; m += 256) { rh[m] = z; rl[m] = z; }
        return;
    }

    __shared__ float e_n[16];
    __shared__ float sE[256 * DDIM];
    __shared__ float red[256];

    if (tid < DDIM) e_n[tid] = E[n * DDIM + tid];
    __syncthreads();

    float v[20];
    float mx = 0.0f;   // relu >= 0
    for (int j = 0; j < 20; ++j) {
        int m0  = j * 256;
        int cnt = NNODE - m0; if (cnt > 256) cnt = 256;
        __syncthreads();
        for (int idx = tid; idx < cnt * DDIM; idx += 256)
            sE[idx] = E[m0 * DDIM + idx];
        __syncthreads();
        int m = m0 + tid;
        if (m < NNODE) {
            float dot = 0.0f;
            #pragma unroll
            for (int d = 0; d < DDIM; ++d) dot += e_n[d] * sE[tid * DDIM + d];
            dot = fmaxf(dot, 0.0f);
            v[j] = dot;
            mx = fmaxf(mx, dot);
        } else v[j] = 0.0f;
    }

    red[tid] = mx; __syncthreads();
    for (int s = 128; s > 0; s >>= 1) {
        if (tid < s) red[tid] = fmaxf(red[tid], red[tid + s]);
        __syncthreads();
    }
    mx = red[0];
    __syncthreads();

    float sum = 0.0f;
    #pragma unroll
    for (int j = 0; j < 20; ++j) {
        int m = j * 256 + tid;
        if (m < NNODE) { v[j] = __expf(v[j] - mx); sum += v[j]; }
    }
    red[tid] = sum; __syncthreads();
    for (int s = 128; s > 0; s >>= 1) {
        if (tid < s) red[tid] += red[tid + s];
        __syncthreads();
    }
    const float inv = 1.0f / red[0];

    #pragma unroll
    for (int j = 0; j < 20; ++j) {
        int m = j * 256 + tid;
        if (m < NNODE) {
            float f = v[j] * inv;
            __nv_bfloat16 hi = __float2bfloat16(f);
            __nv_bfloat16 lo = __float2bfloat16(f - __bfloat162float(hi));
            rh[m] = hi; rl[m] = lo;
        } else if (m < KPAD) {
            rh[m] = __float2bfloat16(0.0f);
            rl[m] = __float2bfloat16(0.0f);
        }
    }
}

// ---------------------------------------------------------------------------
// Kernel 2: build B^T hi/lo: Bmat[col][k] = x[b,k,c], col = b*64+c, padded K.
// ---------------------------------------------------------------------------
__global__ __launch_bounds__(256)
void convert_b_kernel(const float* __restrict__ X)
{
    __shared__ float t[32][33];
    const int tx = threadIdx.x, ty = threadIdx.y;
    const int c0 = blockIdx.x * 32;
    const int k0 = blockIdx.y * 32;
    const int b  = c0 >> 6;
    const int cc = c0 & 63;

    #pragma unroll
    for (int i = 0; i < 4; ++i) {
        int row = k0 + ty + i * 8;
        t[ty + i * 8][tx] = (row < NNODE)
            ? X[(size_t)b * PLANE + (size_t)row * CIN + cc + tx] : 0.0f;
    }
    __syncthreads();

    #pragma unroll
    for (int i = 0; i < 4; ++i) {
        int colr = ty + i * 8;
        float v = t[tx][colr];
        __nv_bfloat16 hi = __float2bfloat16(v);
        __nv_bfloat16 lo = __float2bfloat16(v - __bfloat162float(hi));
        size_t off = (size_t)(c0 + colr) * KPAD + k0 + tx;
        g_Bhi[off] = hi;
        g_Blo[off] = lo;
    }
}

// ---------------------------------------------------------------------------
// Kernel 3: HMMA GEMM  y = support @ x  (3-term bf16 split, fp32 accum)
// mma.sync m16n8k16 + ldmatrix + cp.async, 128x128x32 tiles, 3 stages.
// ---------------------------------------------------------------------------
__device__ __forceinline__ void load_stage(uint32_t sbase, int tid,
                                           int rowBase, int colBase, int k0)
{
    const __nv_bfloat16* gA[2] = { g_Ahi, g_Alo };
    const __nv_bfloat16* gB[2] = { g_Bhi, g_Blo };
    #pragma unroll
    for (int t = 0; t < 2; ++t) {
        #pragma unroll
        for (int i = 0; i < 2; ++i) {
            int seg = tid + i * 256;          // 0..511
            int r = seg >> 2, s = seg & 3;
            const void* g = gA[t] + (size_t)(rowBase + r) * KPAD + k0 + s * 8;
            CPASYNC16(sbase + t * TILE_B + r * APITCH + s * 16, g);
        }
    }
    #pragma unroll
    for (int t = 0; t < 2; ++t) {
        #pragma unroll
        for (int i = 0; i < 2; ++i) {
            int seg = tid + i * 256;
            int r = seg >> 2, s = seg & 3;
            const void* g = gB[t] + (size_t)(colBase + r) * KPAD + k0 + s * 8;
            CPASYNC16(sbase + (2 + t) * TILE_B + r * APITCH + s * 16, g);
        }
    }
}

__global__ void __launch_bounds__(256, 1)
gemm_kernel()
{
    extern __shared__ char dsmem[];
    const uint32_t sb = smem_u32(dsmem);
    const int tid  = threadIdx.x;
    const int warp = tid >> 5;
    const int lane = tid & 31;
    const int wm   = (warp & 3) * 32;   // warp m offset
    const int wn   = (warp >> 2) * 64;  // warp n offset

    // Grid swizzle: groups of 8 column-tiles keep B panels L2-resident.
    const int bid = blockIdx.y * gridDim.x + blockIdx.x;
    const int per = 8 * (MPAD / BM);            // 320
    const int grp = bid / per;
    const int rem = bid % per;
    const int rowBase = (rem / 8) * BM;
    const int colBase = (grp * 8 + (rem & 7)) * BN;

    float acc[2][8][4];
    #pragma unroll
    for (int i = 0; i < 2; ++i)
        #pragma unroll
        for (int j = 0; j < 8; ++j)
            #pragma unroll
            for (int q = 0; q < 4; ++q) acc[i][j][q] = 0.0f;

    // Prologue: fill STAGES-1 stages
    load_stage(sb + 0 * STAGE_B, tid, rowBase, colBase, 0);
    asm volatile("cp.async.commit_group;");
    load_stage(sb + 1 * STAGE_B, tid, rowBase, colBase, BKC);
    asm volatile("cp.async.commit_group;");

    // Precomputed intra-stage fragment addresses (byte offsets)
    const uint32_t aRowOff = (uint32_t)((wm + (lane & 15)) * APITCH + ((lane >> 4) << 4));
    const uint32_t bRowOff = (uint32_t)((wn + ((lane >> 4) << 3) + (lane & 7)) * APITCH
                                        + (((lane >> 3) & 1) << 4));

    for (int ck = 0; ck < NKCH; ++ck) {
        asm volatile("cp.async.wait_group 1;");
        __syncthreads();

        if (ck + 2 < NKCH) {
            load_stage(sb + ((ck + 2) % STAGES) * STAGE_B, tid, rowBase, colBase,
                       (ck + 2) * BKC);
        }
        asm volatile("cp.async.commit_group;");

        const uint32_t st = sb + (ck % STAGES) * STAGE_B;
        const uint32_t sAh = st + 0 * TILE_B + aRowOff;
        const uint32_t sAl = st + 1 * TILE_B + aRowOff;
        const uint32_t sBh = st + 2 * TILE_B + bRowOff;
        const uint32_t sBl = st + 3 * TILE_B + bRowOff;

        #pragma unroll
        for (int ks = 0; ks < 2; ++ks) {
            const uint32_t kb = ks * 32;
            uint32_t ah[2][4], al[2][4], bh[4][4], bl[4][4];
            #pragma unroll
            for (int mt = 0; mt < 2; ++mt) {
                LDSM4(ah[mt][0], ah[mt][1], ah[mt][2], ah[mt][3],
                      sAh + mt * 16 * APITCH + kb);
                LDSM4(al[mt][0], al[mt][1], al[mt][2], al[mt][3],
                      sAl + mt * 16 * APITCH + kb);
            }
            #pragma unroll
            for (int np = 0; np < 4; ++np) {
                LDSM4(bh[np][0], bh[np][1], bh[np][2], bh[np][3],
                      sBh + np * 16 * APITCH + kb);
                LDSM4(bl[np][0], bl[np][1], bl[np][2], bl[np][3],
                      sBl + np * 16 * APITCH + kb);
            }
            #pragma unroll
            for (int mt = 0; mt < 2; ++mt) {
                #pragma unroll
                for (int nt = 0; nt < 8; ++nt) {
                    const int np = nt >> 1, j = (nt & 1) * 2;
                    MMA16816(acc[mt][nt], ah[mt], bh[np][j], bh[np][j + 1]);
                    MMA16816(acc[mt][nt], al[mt], bh[np][j], bh[np][j + 1]);
                    MMA16816(acc[mt][nt], ah[mt], bl[np][j], bl[np][j + 1]);
                }
            }
        }
        __syncthreads();
    }

    // Epilogue: write y[col>>6][m][col&63]
    #pragma unroll
    for (int mt = 0; mt < 2; ++mt) {
        #pragma unroll
        for (int nt = 0; nt < 8; ++nt) {
            const int m   = rowBase + wm + mt * 16 + (lane >> 2);
            const int col = colBase + wn + nt * 8 + (lane & 3) * 2;
            const int b = col >> 6, c = col & 63;
            float* base = g_y + (size_t)b * PLANE + c;
            if (m < NNODE)
                *(float2*)(base + (size_t)m * CIN) =
                    make_float2(acc[mt][nt][0], acc[mt][nt][1]);
            if (m + 8 < NNODE)
                *(float2*)(base + (size_t)(m + 8) * CIN) =
                    make_float2(acc[mt][nt][2], acc[mt][nt][3]);
        }
    }
}

// ---------------------------------------------------------------------------
// Kernel 4: per-node contraction + bias (unchanged).
// ---------------------------------------------------------------------------
__global__ __launch_bounds__(256)
void node_mlp_kernel(const float* __restrict__ X,
                     const float* __restrict__ E,
                     const float* __restrict__ wp,
                     const float* __restrict__ bp,
                     float* __restrict__ out)
{
    extern __shared__ char dsmem[];
    float* s_mem = (float*)dsmem;
    const int n   = blockIdx.x;
    const int tid = threadIdx.x;

    float* Wsh = s_mem;          // [128][64]
    float* Ash = s_mem + 8192;   // [128][64]
    __shared__ float e_sh[DDIM];

    if (tid < DDIM) e_sh[tid] = E[n * DDIM + tid];
    __syncthreads();

    #pragma unroll
    for (int idx = tid; idx < 8192; idx += 256) {
        float s = 0.0f;
        #pragma unroll
        for (int d = 0; d < DDIM; ++d) s += e_sh[d] * wp[d * 8192 + idx];
        Wsh[idx] = s;
    }

    #pragma unroll
    for (int idx = tid; idx < 2048; idx += 256) {
        int b  = idx >> 5;
        int i4 = (idx & 31) * 4;
        float4 vv;
        if (i4 < 64)
            vv = *(const float4*)(X + (size_t)b * PLANE + (size_t)n * CIN + i4);
        else
            vv = *(const float4*)(g_y + (size_t)b * PLANE + (size_t)n * CIN + (i4 - 64));
        Ash[(i4 + 0) * 64 + b] = vv.x;
        Ash[(i4 + 1) * 64 + b] = vv.y;
        Ash[(i4 + 2) * 64 + b] = vv.z;
        Ash[(i4 + 3) * 64 + b] = vv.w;
    }
    __syncthreads();

    const int tb = (tid >> 4) * 4;
    const int to = (tid & 15) * 4;

    float acc[4][4];
    #pragma unroll
    for (int i = 0; i < 4; ++i)
        #pragma unroll
        for (int j = 0; j < 4; ++j) acc[i][j] = 0.0f;

    #pragma unroll 4
    for (int ki = 0; ki < 128; ++ki) {
        float4 a = *(const float4*)&Ash[ki * 64 + tb];
        float4 w = *(const float4*)&Wsh[ki * 64 + to];
        float aa[4] = {a.x, a.y, a.z, a.w};
        float ww[4] = {w.x, w.y, w.z, w.w};
        #pragma unroll
        for (int i = 0; i < 4; ++i)
            #pragma unroll
            for (int j = 0; j < 4; ++j)
                acc[i][j] += aa[i] * ww[j];
    }

    float bias[4];
    #pragma unroll
    for (int j = 0; j < 4; ++j) {
        float s = 0.0f;
        #pragma unroll
        for (int d = 0; d < DDIM; ++d) s += e_sh[d] * bp[d * COUT + to + j];
        bias[j] = s;
    }

    #pragma unroll
    for (int i = 0; i < 4; ++i) {
        float4 vv = make_float4(acc[i][0] + bias[0], acc[i][1] + bias[1],
                                acc[i][2] + bias[2], acc[i][3] + bias[3]);
        *(float4*)(out + (size_t)(tb + i) * PLANE + (size_t)n * COUT + to) = vv;
    }
}

// ---------------------------------------------------------------------------
extern "C" void kernel_launch(void* const* d_in, const int* in_sizes, int n_in,
                              void* d_out, int out_size)
{
    const float* x  = (const float*)d_in[0];   // (64, 5000, 64)
    const float* E  = (const float*)d_in[1];   // (5000, 10)
    const float* wp = (const float*)d_in[2];   // (10, 2, 64, 64)
    const float* bp = (const float*)d_in[3];   // (10, 64)
    float* out = (float*)d_out;                // (64, 5000, 64)

    // 1) softmax(relu(E E^T)) rows -> bf16 hi/lo (padded)
    support_split_kernel<<<MPAD, 256>>>(E);

    // 2) transpose x -> B^T hi/lo (K-major, padded)
    dim3 gB(NCOLS / 32, KPAD / 32);
    convert_b_kernel<<<gB, dim3(32, 8)>>>(x);

    // 3) tensor-core GEMM (HMMA): y = support @ x
    cudaFuncSetAttribute(gemm_kernel,
                         cudaFuncAttributeMaxDynamicSharedMemorySize, GEMM_SMEM);
    dim3 gG(NCOLS / BN, MPAD / BM);
    gemm_kernel<<<gG, 256, GEMM_SMEM>>>();

    // 4) per-node contraction + bias
    cudaFuncSetAttribute(node_mlp_kernel,
                         cudaFuncAttributeMaxDynamicSharedMemorySize, 65536);
    node_mlp_kernel<<<NNODE, 256, 65536>>>(x, E, wp, bp, out);
}

// round 4
// speedup vs baseline: 2.6335x; 1.1600x over previous
#include <cuda_runtime.h>
#include <cuda_bf16.h>
#include <cstdint>

// Problem constants
#define BATCH   64
#define NNODE   5000
#define CIN     64
#define COUT    64
#define DDIM    10
#define PLANE   (NNODE * CIN)       // 320000
#define NCOLS   (BATCH * CIN)       // 4096 GEMM output columns

// Padded GEMM dims
#define KPAD    5056                // 158 * 32
#define MPAD    5120                // 40 * 128

// GEMM tiling
#define BM      128
#define BN      128
#define BKC     32
#define NKCH    (KPAD / BKC)        // 158
#define STAGES  2

#define APITCH  80                  // bytes per smem row (64B payload + 16B pad)
#define TILE_B  (128 * APITCH)      // 10240 B per tile
#define STAGE_B (4 * TILE_B)        // Ah, Al, Bh, Bl
#define GEMM_SMEM (STAGES * STAGE_B)  // 81920 B -> 2 CTAs/SM

// ---------------------------------------------------------------------------
// Device-global scratch (no allocations allowed)
// ---------------------------------------------------------------------------
__device__ __align__(256) __nv_bfloat16 g_Ahi[(size_t)MPAD * KPAD];
__device__ __align__(256) __nv_bfloat16 g_Alo[(size_t)MPAD * KPAD];
__device__ __align__(256) __nv_bfloat16 g_Bhi[(size_t)NCOLS * KPAD];
__device__ __align__(256) __nv_bfloat16 g_Blo[(size_t)NCOLS * KPAD];
__device__ __align__(256) float         g_y[(size_t)BATCH * PLANE];
// per-node transposed weights W_T[n][o][ki], bf16 hi/lo split
__device__ __align__(256) __nv_bfloat16 g_Wh[(size_t)NNODE * 8192];
__device__ __align__(256) __nv_bfloat16 g_Wl[(size_t)NNODE * 8192];

// ---------------------------------------------------------------------------
__device__ __forceinline__ uint32_t smem_u32(const void* p) {
    uint32_t a;
    asm("{ .reg .u64 t; cvta.to.shared.u64 t, %1; cvt.u32.u64 %0, t; }"
        : "=r"(a) : "l"(p));
    return a;
}

#define LDSM4(r0, r1, r2, r3, addr) \
    asm volatile("ldmatrix.sync.aligned.m8n8.x4.shared.b16 {%0,%1,%2,%3}, [%4];" \
                 : "=r"(r0), "=r"(r1), "=r"(r2), "=r"(r3) : "r"(addr))

#define MMA16816(d, a, b0, b1) \
    asm volatile("mma.sync.aligned.m16n8k16.row.col.f32.bf16.bf16.f32 " \
                 "{%0,%1,%2,%3}, {%4,%5,%6,%7}, {%8,%9}, {%0,%1,%2,%3};" \
                 : "+f"((d)[0]), "+f"((d)[1]), "+f"((d)[2]), "+f"((d)[3]) \
                 : "r"((a)[0]), "r"((a)[1]), "r"((a)[2]), "r"((a)[3]), \
                   "r"(b0), "r"(b1))

#define CPASYNC16(saddr, gaddr) \
    asm volatile("cp.async.cg.shared.global [%0], [%1], 16;" \
                 :: "r"(saddr), "l"(gaddr))

__device__ __forceinline__ void bf16_split(float f, __nv_bfloat16& hi, __nv_bfloat16& lo) {
    hi = __float2bfloat16(f);
    lo = __float2bfloat16(f - __bfloat162float(hi));
}

// ---------------------------------------------------------------------------
// Kernel 1: softmax(relu(E E^T)) row -> bf16 hi/lo, padded rows into g_Ahi/lo.
// ---------------------------------------------------------------------------
__global__ __launch_bounds__(256)
void support_split_kernel(const float* __restrict__ E)
{
    const int n   = blockIdx.x;
    const int tid = threadIdx.x;
    __nv_bfloat16* rh = g_Ahi + (size_t)n * KPAD;
    __nv_bfloat16* rl = g_Alo + (size_t)n * KPAD;

    if (n >= NNODE) {
        const __nv_bfloat16 z = __float2bfloat16(0.0f);
        for (int m = tid; m < KPAD; m += 256) { rh[m] = z; rl[m] = z; }
        return;
    }

    __shared__ float e_n[16];
    __shared__ float sE[256 * DDIM];
    __shared__ float red[256];

    if (tid < DDIM) e_n[tid] = E[n * DDIM + tid];
    __syncthreads();

    float v[20];
    float mx = 0.0f;   // relu >= 0
    for (int j = 0; j < 20; ++j) {
        int m0  = j * 256;
        int cnt = NNODE - m0; if (cnt > 256) cnt = 256;
        __syncthreads();
        for (int idx = tid; idx < cnt * DDIM; idx += 256)
            sE[idx] = E[m0 * DDIM + idx];
        __syncthreads();
        int m = m0 + tid;
        if (m < NNODE) {
            float dot = 0.0f;
            #pragma unroll
            for (int d = 0; d < DDIM; ++d) dot += e_n[d] * sE[tid * DDIM + d];
            dot = fmaxf(dot, 0.0f);
            v[j] = dot;
            mx = fmaxf(mx, dot);
        } else v[j] = 0.0f;
    }

    red[tid] = mx; __syncthreads();
    for (int s = 128; s > 0; s >>= 1) {
        if (tid < s) red[tid] = fmaxf(red[tid], red[tid + s]);
        __syncthreads();
    }
    mx = red[0];
    __syncthreads();

    float sum = 0.0f;
    #pragma unroll
    for (int j = 0; j < 20; ++j) {
        int m = j * 256 + tid;
        if (m < NNODE) { v[j] = __expf(v[j] - mx); sum += v[j]; }
    }
    red[tid] = sum; __syncthreads();
    for (int s = 128; s > 0; s >>= 1) {
        if (tid < s) red[tid] += red[tid + s];
        __syncthreads();
    }
    const float inv = 1.0f / red[0];

    #pragma unroll
    for (int j = 0; j < 20; ++j) {
        int m = j * 256 + tid;
        if (m < NNODE) {
            __nv_bfloat16 hi, lo;
            bf16_split(v[j] * inv, hi, lo);
            rh[m] = hi; rl[m] = lo;
        } else if (m < KPAD) {
            rh[m] = __float2bfloat16(0.0f);
            rl[m] = __float2bfloat16(0.0f);
        }
    }
}

// ---------------------------------------------------------------------------
// Kernel 2: build B^T hi/lo: Bmat[col][k] = x[b,k,c], col = b*64+c, padded K.
// ---------------------------------------------------------------------------
__global__ __launch_bounds__(256)
void convert_b_kernel(const float* __restrict__ X)
{
    __shared__ float t[32][33];
    const int tx = threadIdx.x, ty = threadIdx.y;
    const int c0 = blockIdx.x * 32;
    const int k0 = blockIdx.y * 32;
    const int b  = c0 >> 6;
    const int cc = c0 & 63;

    #pragma unroll
    for (int i = 0; i < 4; ++i) {
        int row = k0 + ty + i * 8;
        t[ty + i * 8][tx] = (row < NNODE)
            ? X[(size_t)b * PLANE + (size_t)row * CIN + cc + tx] : 0.0f;
    }
    __syncthreads();

    #pragma unroll
    for (int i = 0; i < 4; ++i) {
        int colr = ty + i * 8;
        __nv_bfloat16 hi, lo;
        bf16_split(t[tx][colr], hi, lo);
        size_t off = (size_t)(c0 + colr) * KPAD + k0 + tx;
        g_Bhi[off] = hi;
        g_Blo[off] = lo;
    }
}

// ---------------------------------------------------------------------------
// Kernel 3: W_T build.  W_T[n][o][ki] = sum_d E[n,d] * wp[d][ki][o], bf16 split.
// Grid: (625 node-groups of 8, 8 p-tiles of 1024). p = o*128 + ki.
// ---------------------------------------------------------------------------
__global__ __launch_bounds__(256)
void wbuild_kernel(const float* __restrict__ E, const float* __restrict__ wp)
{
    __shared__ float e_sh[8][DDIM];
    const int tid = threadIdx.x;
    const int n0  = blockIdx.x * 8;

    if (tid < 8 * DDIM) {
        int j = tid / DDIM, d = tid % DDIM;
        e_sh[j][d] = E[(n0 + j) * DDIM + d];
    }
    __syncthreads();

    const int pbase = blockIdx.y * 1024 + tid * 4;
    #pragma unroll
    for (int q = 0; q < 4; ++q) {
        const int p  = pbase + q;
        const int o  = p >> 7;
        const int ki = p & 127;
        float wv[DDIM];
        #pragma unroll
        for (int d = 0; d < DDIM; ++d) wv[d] = wp[d * 8192 + ki * 64 + o];
        #pragma unroll
        for (int j = 0; j < 8; ++j) {
            float s = 0.0f;
            #pragma unroll
            for (int d = 0; d < DDIM; ++d) s += e_sh[j][d] * wv[d];
            __nv_bfloat16 hi, lo;
            bf16_split(s, hi, lo);
            size_t off = (size_t)(n0 + j) * 8192 + p;
            g_Wh[off] = hi;
            g_Wl[off] = lo;
        }
    }
}

// ---------------------------------------------------------------------------
// Kernel 4: HMMA GEMM  y = support @ x  (3-term bf16 split, fp32 accum)
// 128x128x32 tiles, 2 stages, 2 CTAs/SM.
// ---------------------------------------------------------------------------
__device__ __forceinline__ void load_stage(uint32_t sbase, int tid,
                                           int rowBase, int colBase, int k0)
{
    const __nv_bfloat16* gA[2] = { g_Ahi, g_Alo };
    const __nv_bfloat16* gB[2] = { g_Bhi, g_Blo };
    #pragma unroll
    for (int t = 0; t < 2; ++t) {
        #pragma unroll
        for (int i = 0; i < 2; ++i) {
            int seg = tid + i * 256;          // 0..511
            int r = seg >> 2, s = seg & 3;
            const void* g = gA[t] + (size_t)(rowBase + r) * KPAD + k0 + s * 8;
            CPASYNC16(sbase + t * TILE_B + r * APITCH + s * 16, g);
        }
    }
    #pragma unroll
    for (int t = 0; t < 2; ++t) {
        #pragma unroll
        for (int i = 0; i < 2; ++i) {
            int seg = tid + i * 256;
            int r = seg >> 2, s = seg & 3;
            const void* g = gB[t] + (size_t)(colBase + r) * KPAD + k0 + s * 8;
            CPASYNC16(sbase + (2 + t) * TILE_B + r * APITCH + s * 16, g);
        }
    }
}

__global__ void __launch_bounds__(256, 2)
gemm_kernel()
{
    extern __shared__ char dsmem[];
    const uint32_t sb = smem_u32(dsmem);
    const int tid  = threadIdx.x;
    const int warp = tid >> 5;
    const int lane = tid & 31;
    const int wm   = (warp & 3) * 32;   // warp m offset
    const int wn   = (warp >> 2) * 64;  // warp n offset

    // Grid swizzle: groups of 8 column-tiles keep B panels L2-resident.
    const int bid = blockIdx.y * gridDim.x + blockIdx.x;
    const int per = 8 * (MPAD / BM);            // 320
    const int grp = bid / per;
    const int rem = bid % per;
    const int rowBase = (rem / 8) * BM;
    const int colBase = (grp * 8 + (rem & 7)) * BN;

    float acc[2][8][4];
    #pragma unroll
    for (int i = 0; i < 2; ++i)
        #pragma unroll
        for (int j = 0; j < 8; ++j)
            #pragma unroll
            for (int q = 0; q < 4; ++q) acc[i][j][q] = 0.0f;

    // Prologue: fill stage 0
    load_stage(sb, tid, rowBase, colBase, 0);
    asm volatile("cp.async.commit_group;");

    const uint32_t aRowOff = (uint32_t)((wm + (lane & 15)) * APITCH + ((lane >> 4) << 4));
    const uint32_t bRowOff = (uint32_t)((wn + ((lane >> 4) << 3) + (lane & 7)) * APITCH
                                        + (((lane >> 3) & 1) << 4));

    for (int ck = 0; ck < NKCH; ++ck) {
        if (ck + 1 < NKCH) {
            load_stage(sb + ((ck + 1) & 1) * STAGE_B, tid, rowBase, colBase,
                       (ck + 1) * BKC);
            asm volatile("cp.async.commit_group;");
            asm volatile("cp.async.wait_group 1;");
        } else {
            asm volatile("cp.async.wait_group 0;");
        }
        __syncthreads();

        const uint32_t st = sb + (ck & 1) * STAGE_B;
        const uint32_t sAh = st + 0 * TILE_B + aRowOff;
        const uint32_t sAl = st + 1 * TILE_B + aRowOff;
        const uint32_t sBh = st + 2 * TILE_B + bRowOff;
        const uint32_t sBl = st + 3 * TILE_B + bRowOff;

        #pragma unroll
        for (int ks = 0; ks < 2; ++ks) {
            const uint32_t kb = ks * 32;
            uint32_t ah[2][4], al[2][4];
            #pragma unroll
            for (int mt = 0; mt < 2; ++mt) {
                LDSM4(ah[mt][0], ah[mt][1], ah[mt][2], ah[mt][3],
                      sAh + mt * 16 * APITCH + kb);
                LDSM4(al[mt][0], al[mt][1], al[mt][2], al[mt][3],
                      sAl + mt * 16 * APITCH + kb);
            }
            #pragma unroll
            for (int np = 0; np < 4; ++np) {
                uint32_t bh[4], bl[4];
                LDSM4(bh[0], bh[1], bh[2], bh[3], sBh + np * 16 * APITCH + kb);
                LDSM4(bl[0], bl[1], bl[2], bl[3], sBl + np * 16 * APITCH + kb);
                #pragma unroll
                for (int mt = 0; mt < 2; ++mt) {
                    #pragma unroll
                    for (int j = 0; j < 2; ++j) {
                        const int nt = np * 2 + j;
                        MMA16816(acc[mt][nt], ah[mt], bh[j * 2], bh[j * 2 + 1]);
                        MMA16816(acc[mt][nt], al[mt], bh[j * 2], bh[j * 2 + 1]);
                        MMA16816(acc[mt][nt], ah[mt], bl[j * 2], bl[j * 2 + 1]);
                    }
                }
            }
        }
        __syncthreads();
    }

    // Epilogue: write y[col>>6][m][col&63]
    #pragma unroll
    for (int mt = 0; mt < 2; ++mt) {
        #pragma unroll
        for (int nt = 0; nt < 8; ++nt) {
            const int m   = rowBase + wm + mt * 16 + (lane >> 2);
            const int col = colBase + wn + nt * 8 + (lane & 3) * 2;
            const int b = col >> 6, c = col & 63;
            float* base = g_y + (size_t)b * PLANE + c;
            if (m < NNODE)
                *(float2*)(base + (size_t)m * CIN) =
                    make_float2(acc[mt][nt][0], acc[mt][nt][1]);
            if (m + 8 < NNODE)
                *(float2*)(base + (size_t)(m + 8) * CIN) =
                    make_float2(acc[mt][nt][2], acc[mt][nt][3]);
        }
    }
}

// ---------------------------------------------------------------------------
// Kernel 5: per-node HMMA.  out[b,n,o] = A_n(64x128) @ W_n(128x64) + bias_n.
// A rows = batch, cols ki (x | y), bf16 hi/lo built in smem.
// W from g_Wh/g_Wl ([o][ki] layout = mma col-major B operand).
// ---------------------------------------------------------------------------
#define NPITCH 272                       // 256B payload + 16B pad
#define NSM_AH 0
#define NSM_AL (64 * NPITCH)             // 17408
#define NSM_WH (2 * 64 * NPITCH)         // 34816
#define NSM_WL (3 * 64 * NPITCH)         // 52224
#define NSM_TOT (4 * 64 * NPITCH)        // 69632

__global__ void __launch_bounds__(256, 2)
node_mma_kernel(const float* __restrict__ X,
                const float* __restrict__ E,
                const float* __restrict__ bp,
                float* __restrict__ out)
{
    extern __shared__ char dsmem[];
    const uint32_t sb = smem_u32(dsmem);
    __shared__ float e_sh[DDIM];
    __shared__ float bias_sh[64];

    const int n    = blockIdx.x;
    const int tid  = threadIdx.x;
    const int warp = tid >> 5;
    const int lane = tid & 31;

    if (tid < DDIM) e_sh[tid] = E[n * DDIM + tid];

    // Stage W hi/lo: 16 KB each, uint4 copies. 1024 segs of 16B per matrix.
    {
        const uint4* wh = (const uint4*)(g_Wh + (size_t)n * 8192);
        const uint4* wl = (const uint4*)(g_Wl + (size_t)n * 8192);
        #pragma unroll
        for (int i = 0; i < 4; ++i) {
            int seg = tid + i * 256;         // 0..1023
            int o = seg >> 4, s = seg & 15;
            *(uint4*)(dsmem + NSM_WH + o * NPITCH + s * 16) = wh[seg];
            *(uint4*)(dsmem + NSM_WL + o * NPITCH + s * 16) = wl[seg];
        }
    }

    // Stage A hi/lo: rows b (64), 128 ki = [x row | y row], split to bf16.
    #pragma unroll
    for (int idx = tid; idx < 2048; idx += 256) {
        int b  = idx >> 5;
        int i4 = (idx & 31) * 4;             // ki base, 0..124
        float4 vv;
        if (i4 < 64)
            vv = *(const float4*)(X + (size_t)b * PLANE + (size_t)n * CIN + i4);
        else
            vv = *(const float4*)(g_y + (size_t)b * PLANE + (size_t)n * CIN + (i4 - 64));
        __nv_bfloat16 h[4], l[4];
        bf16_split(vv.x, h[0], l[0]);
        bf16_split(vv.y, h[1], l[1]);
        bf16_split(vv.z, h[2], l[2]);
        bf16_split(vv.w, h[3], l[3]);
        *(uint2*)(dsmem + NSM_AH + b * NPITCH + i4 * 2) = *(const uint2*)h;
        *(uint2*)(dsmem + NSM_AL + b * NPITCH + i4 * 2) = *(const uint2*)l;
    }

    __syncthreads();
    if (tid < 64) {
        float s = 0.0f;
        #pragma unroll
        for (int d = 0; d < DDIM; ++d) s += e_sh[d] * bp[d * COUT + tid];
        bias_sh[tid] = s;
    }

    const int wm = (warp & 3) * 16;          // 4 m-tiles of 16 rows
    const int wn = (warp >> 2) * 32;         // 2 n-halves of 32 cols

    const uint32_t aOff = sb + NSM_AH
        + (uint32_t)((wm + (lane & 15)) * NPITCH + ((lane >> 4) << 4));
    const uint32_t bOff = sb + NSM_WH
        + (uint32_t)((wn + ((lane >> 4) << 3) + (lane & 7)) * NPITCH
                     + (((lane >> 3) & 1) << 4));

    float acc[4][4];
    #pragma unroll
    for (int j = 0; j < 4; ++j)
        #pragma unroll
        for (int q = 0; q < 4; ++q) acc[j][q] = 0.0f;

    #pragma unroll
    for (int ks = 0; ks < 8; ++ks) {
        const uint32_t kb = ks * 32;
        uint32_t ah[4], al[4];
        LDSM4(ah[0], ah[1], ah[2], ah[3], aOff + kb);
        LDSM4(al[0], al[1], al[2], al[3], aOff + (NSM_AL - NSM_AH) + kb);
        #pragma unroll
        for (int np = 0; np < 2; ++np) {
            uint32_t bh[4], bl[4];
            LDSM4(bh[0], bh[1], bh[2], bh[3], bOff + np * 16 * NPITCH + kb);
            LDSM4(bl[0], bl[1], bl[2], bl[3],
                  bOff + (NSM_WL - NSM_WH) + np * 16 * NPITCH + kb);
            #pragma unroll
            for (int j = 0; j < 2; ++j) {
                const int nt = np * 2 + j;
                MMA16816(acc[nt], ah, bh[j * 2], bh[j * 2 + 1]);
                MMA16816(acc[nt], al, bh[j * 2], bh[j * 2 + 1]);
                MMA16816(acc[nt], ah, bl[j * 2], bl[j * 2 + 1]);
            }
        }
    }

    __syncthreads();   // bias_sh ready (cheap; also covers smem reuse)

    #pragma unroll
    for (int nt = 0; nt < 4; ++nt) {
        const int m   = wm + (lane >> 2);
        const int col = wn + nt * 8 + (lane & 3) * 2;
        const float b0 = bias_sh[col], b1 = bias_sh[col + 1];
        float* base = out + (size_t)n * COUT + col;
        *(float2*)(base + (size_t)m * PLANE) =
            make_float2(acc[nt][0] + b0, acc[nt][1] + b1);
        *(float2*)(base + (size_t)(m + 8) * PLANE) =
            make_float2(acc[nt][2] + b0, acc[nt][3] + b1);
    }
}

// ---------------------------------------------------------------------------
extern "C" void kernel_launch(void* const* d_in, const int* in_sizes, int n_in,
                              void* d_out, int out_size)
{
    const float* x  = (const float*)d_in[0];   // (64, 5000, 64)
    const float* E  = (const float*)d_in[1];   // (5000, 10)
    const float* wp = (const float*)d_in[2];   // (10, 2, 64, 64)
    const float* bp = (const float*)d_in[3];   // (10, 64)
    float* out = (float*)d_out;                // (64, 5000, 64)

    // 1) softmax(relu(E E^T)) rows -> bf16 hi/lo (padded)
    support_split_kernel<<<MPAD, 256>>>(E);

    // 2) transpose x -> B^T hi/lo (K-major, padded)
    dim3 gB(NCOLS / 32, KPAD / 32);
    convert_b_kernel<<<gB, dim3(32, 8)>>>(x);

    // 3) per-node weights W_T (bf16 hi/lo)
    dim3 gW(NNODE / 8, 8);
    wbuild_kernel<<<gW, 256>>>(E, wp);

    // 4) tensor-core GEMM (HMMA): y = support @ x
    cudaFuncSetAttribute(gemm_kernel,
                         cudaFuncAttributeMaxDynamicSharedMemorySize, GEMM_SMEM);
    dim3 gG(NCOLS / BN, MPAD / BM);
    gemm_kernel<<<gG, 256, GEMM_SMEM>>>();

    // 5) per-node HMMA contraction + bias
    cudaFuncSetAttribute(node_mma_kernel,
                         cudaFuncAttributeMaxDynamicSharedMemorySize, NSM_TOT);
    node_mma_kernel<<<NNODE, 256, NSM_TOT>>>(x, E, bp, out);
}

// round 7
// speedup vs baseline: 2.7015x; 1.0258x over previous
#include <cuda_runtime.h>
#include <cuda_bf16.h>
#include <cstdint>

// Problem constants
#define BATCH   64
#define NNODE   5000
#define CIN     64
#define COUT    64
#define DDIM    10
#define PLANE   (NNODE * CIN)       // 320000
#define NCOLS   (BATCH * CIN)       // 4096 GEMM output columns

// Padded GEMM dims
#define KPAD    5056                // 158 * 32
#define MPAD    5120                // 40 * 128

// GEMM tiling: 128x128 CTA tile, 4 warps of 64x64, 128 threads.
#define BM      128
#define BN      128
#define BKC     32
#define NKCH    (KPAD / BKC)        // 158
#define STAGES  2

#define APITCH  80                  // bytes per smem row (64B payload + 16B pad)
#define TILE_B  (128 * APITCH)      // 10240 B per tile
#define STAGE_B (4 * TILE_B)        // Ah, Al, Bh, Bl
#define GEMM_SMEM (STAGES * STAGE_B)  // 81920 B -> 2 CTAs/SM

// ---------------------------------------------------------------------------
// Device-global scratch (no allocations allowed)
// ---------------------------------------------------------------------------
__device__ __align__(256) __nv_bfloat16 g_Ahi[(size_t)MPAD * KPAD];
__device__ __align__(256) __nv_bfloat16 g_Alo[(size_t)MPAD * KPAD];
__device__ __align__(256) __nv_bfloat16 g_Bhi[(size_t)NCOLS * KPAD];
__device__ __align__(256) __nv_bfloat16 g_Blo[(size_t)NCOLS * KPAD];
__device__ __align__(256) float         g_y[(size_t)BATCH * PLANE];
// per-node transposed weights W_T[n][o][ki], bf16 hi/lo split
__device__ __align__(256) __nv_bfloat16 g_Wh[(size_t)NNODE * 8192];
__device__ __align__(256) __nv_bfloat16 g_Wl[(size_t)NNODE * 8192];

// ---------------------------------------------------------------------------
__device__ __forceinline__ uint32_t smem_u32(const void* p) {
    uint32_t a;
    asm("{ .reg .u64 t; cvta.to.shared.u64 t, %1; cvt.u32.u64 %0, t; }"
        : "=r"(a) : "l"(p));
    return a;
}

#define LDSM4(r0, r1, r2, r3, addr) \
    asm volatile("ldmatrix.sync.aligned.m8n8.x4.shared.b16 {%0,%1,%2,%3}, [%4];" \
                 : "=r"(r0), "=r"(r1), "=r"(r2), "=r"(r3) : "r"(addr))

#define MMA16816(d, a, b0, b1) \
    asm volatile("mma.sync.aligned.m16n8k16.row.col.f32.bf16.bf16.f32 " \
                 "{%0,%1,%2,%3}, {%4,%5,%6,%7}, {%8,%9}, {%0,%1,%2,%3};" \
                 : "+f"((d)[0]), "+f"((d)[1]), "+f"((d)[2]), "+f"((d)[3]) \
                 : "r"((a)[0]), "r"((a)[1]), "r"((a)[2]), "r"((a)[3]), \
                   "r"(b0), "r"(b1))

#define CPASYNC16(saddr, gaddr) \
    asm volatile("cp.async.cg.shared.global [%0], [%1], 16;" \
                 :: "r"(saddr), "l"(gaddr))

__device__ __forceinline__ void bf16_split(float f, __nv_bfloat16& hi, __nv_bfloat16& lo) {
    hi = __float2bfloat16(f);
    lo = __float2bfloat16(f - __bfloat162float(hi));
}

// ---------------------------------------------------------------------------
// Kernel 1: softmax(relu(E E^T)) row -> bf16 hi/lo, padded rows into g_Ahi/lo.
// ---------------------------------------------------------------------------
__global__ __launch_bounds__(256)
void support_split_kernel(const float* __restrict__ E)
{
    const int n   = blockIdx.x;
    const int tid = threadIdx.x;
    __nv_bfloat16* rh = g_Ahi + (size_t)n * KPAD;
    __nv_bfloat16* rl = g_Alo + (size_t)n * KPAD;

    if (n >= NNODE) {
        const __nv_bfloat16 z = __float2bfloat16(0.0f);
        for (int m = tid; m < KPAD; m += 256) { rh[m] = z; rl[m] = z; }
        return;
    }

    __shared__ float e_n[16];
    __shared__ float sE[256 * DDIM];
    __shared__ float red[256];

    if (tid < DDIM) e_n[tid] = E[n * DDIM + tid];
    __syncthreads();

    float v[20];
    float mx = 0.0f;   // relu >= 0
    for (int j = 0; j < 20; ++j) {
        int m0  = j * 256;
        int cnt = NNODE - m0; if (cnt > 256) cnt = 256;
        __syncthreads();
        for (int idx = tid; idx < cnt * DDIM; idx += 256)
            sE[idx] = E[m0 * DDIM + idx];
        __syncthreads();
        int m = m0 + tid;
        if (m < NNODE) {
            float dot = 0.0f;
            #pragma unroll
            for (int d = 0; d < DDIM; ++d) dot += e_n[d] * sE[tid * DDIM + d];
            dot = fmaxf(dot, 0.0f);
            v[j] = dot;
            mx = fmaxf(mx, dot);
        } else v[j] = 0.0f;
    }

    red[tid] = mx; __syncthreads();
    for (int s = 128; s > 0; s >>= 1) {
        if (tid < s) red[tid] = fmaxf(red[tid], red[tid + s]);
        __syncthreads();
    }
    mx = red[0];
    __syncthreads();

    float sum = 0.0f;
    #pragma unroll
    for (int j = 0; j < 20; ++j) {
        int m = j * 256 + tid;
        if (m < NNODE) { v[j] = __expf(v[j] - mx); sum += v[j]; }
    }
    red[tid] = sum; __syncthreads();
    for (int s = 128; s > 0; s >>= 1) {
        if (tid < s) red[tid] += red[tid + s];
        __syncthreads();
    }
    const float inv = 1.0f / red[0];

    #pragma unroll
    for (int j = 0; j < 20; ++j) {
        int m = j * 256 + tid;
        if (m < NNODE) {
            __nv_bfloat16 hi, lo;
            bf16_split(v[j] * inv, hi, lo);
            rh[m] = hi; rl[m] = lo;
        } else if (m < KPAD) {
            rh[m] = __float2bfloat16(0.0f);
            rl[m] = __float2bfloat16(0.0f);
        }
    }
}

// ---------------------------------------------------------------------------
// Kernel 2: build B^T hi/lo: Bmat[col][k] = x[b,k,c], col = b*64+c, padded K.
// ---------------------------------------------------------------------------
__global__ __launch_bounds__(256)
void convert_b_kernel(const float* __restrict__ X)
{
    __shared__ float t[32][33];
    const int tx = threadIdx.x, ty = threadIdx.y;
    const int c0 = blockIdx.x * 32;
    const int k0 = blockIdx.y * 32;
    const int b  = c0 >> 6;
    const int cc = c0 & 63;

    #pragma unroll
    for (int i = 0; i < 4; ++i) {
        int row = k0 + ty + i * 8;
        t[ty + i * 8][tx] = (row < NNODE)
            ? X[(size_t)b * PLANE + (size_t)row * CIN + cc + tx] : 0.0f;
    }
    __syncthreads();

    #pragma unroll
    for (int i = 0; i < 4; ++i) {
        int colr = ty + i * 8;
        __nv_bfloat16 hi, lo;
        bf16_split(t[tx][colr], hi, lo);
        size_t off = (size_t)(c0 + colr) * KPAD + k0 + tx;
        g_Bhi[off] = hi;
        g_Blo[off] = lo;
    }
}

// ---------------------------------------------------------------------------
// Kernel 3: W_T build.  W_T[n][o][ki] = sum_d E[n,d] * wp[d][ki][o], bf16 split.
// ---------------------------------------------------------------------------
__global__ __launch_bounds__(256)
void wbuild_kernel(const float* __restrict__ E, const float* __restrict__ wp)
{
    __shared__ float e_sh[8][DDIM];
    const int tid = threadIdx.x;
    const int n0  = blockIdx.x * 8;

    if (tid < 8 * DDIM) {
        int j = tid / DDIM, d = tid % DDIM;
        e_sh[j][d] = E[(n0 + j) * DDIM + d];
    }
    __syncthreads();

    const int pbase = blockIdx.y * 1024 + tid * 4;
    #pragma unroll
    for (int q = 0; q < 4; ++q) {
        const int p  = pbase + q;
        const int o  = p >> 7;
        const int ki = p & 127;
        float wv[DDIM];
        #pragma unroll
        for (int d = 0; d < DDIM; ++d) wv[d] = wp[d * 8192 + ki * 64 + o];
        #pragma unroll
        for (int j = 0; j < 8; ++j) {
            float s = 0.0f;
            #pragma unroll
            for (int d = 0; d < DDIM; ++d) s += e_sh[j][d] * wv[d];
            __nv_bfloat16 hi, lo;
            bf16_split(s, hi, lo);
            size_t off = (size_t)(n0 + j) * 8192 + p;
            g_Wh[off] = hi;
            g_Wl[off] = lo;
        }
    }
}

// ---------------------------------------------------------------------------
// Kernel 4: HMMA GEMM  y = support @ x  (3-term bf16 split, fp32 accum)
// 128x128x32 CTA tiles, 4 warps of 64x64, 128 threads, 2 stages, 2 CTAs/SM.
// ---------------------------------------------------------------------------
__device__ __forceinline__ void load_stage(uint32_t sbase, int tid,
                                           int rowBase, int colBase, int k0)
{
    const __nv_bfloat16* gA[2] = { g_Ahi, g_Alo };
    const __nv_bfloat16* gB[2] = { g_Bhi, g_Blo };
    #pragma unroll
    for (int t = 0; t < 2; ++t) {
        #pragma unroll
        for (int i = 0; i < 4; ++i) {
            int seg = tid + i * 128;          // 0..511
            int r = seg >> 2, s = seg & 3;
            const void* g = gA[t] + (size_t)(rowBase + r) * KPAD + k0 + s * 8;
            CPASYNC16(sbase + t * TILE_B + r * APITCH + s * 16, g);
        }
    }
    #pragma unroll
    for (int t = 0; t < 2; ++t) {
        #pragma unroll
        for (int i = 0; i < 4; ++i) {
            int seg = tid + i * 128;
            int r = seg >> 2, s = seg & 3;
            const void* g = gB[t] + (size_t)(colBase + r) * KPAD + k0 + s * 8;
            CPASYNC16(sbase + (2 + t) * TILE_B + r * APITCH + s * 16, g);
        }
    }
}

__global__ void __launch_bounds__(128, 2)
gemm_kernel()
{
    extern __shared__ char dsmem[];
    const uint32_t sb = smem_u32(dsmem);
    const int tid  = threadIdx.x;
    const int warp = tid >> 5;
    const int lane = tid & 31;
    const int wm   = (warp & 1) * 64;   // warp m offset (2 x 64)
    const int wn   = (warp >> 1) * 64;  // warp n offset (2 x 64)

    // Grid swizzle: groups of 8 column-tiles keep B panels L2-resident.
    const int bid = blockIdx.y * gridDim.x + blockIdx.x;
    const int per = 8 * (MPAD / BM);            // 320
    const int grp = bid / per;
    const int rem = bid % per;
    const int rowBase = (rem / 8) * BM;
    const int colBase = (grp * 8 + (rem & 7)) * BN;

    float acc[4][8][4];
    #pragma unroll
    for (int i = 0; i < 4; ++i)
        #pragma unroll
        for (int j = 0; j < 8; ++j)
            #pragma unroll
            for (int q = 0; q < 4; ++q) acc[i][j][q] = 0.0f;

    // Prologue: fill stage 0
    load_stage(sb, tid, rowBase, colBase, 0);
    asm volatile("cp.async.commit_group;");

    const uint32_t aRowOff = (uint32_t)((wm + (lane & 15)) * APITCH + ((lane >> 4) << 4));
    const uint32_t bRowOff = (uint32_t)((wn + ((lane >> 4) << 3) + (lane & 7)) * APITCH
                                        + (((lane >> 3) & 1) << 4));

    for (int ck = 0; ck < NKCH; ++ck) {
        if (ck + 1 < NKCH) {
            load_stage(sb + ((ck + 1) & 1) * STAGE_B, tid, rowBase, colBase,
                       (ck + 1) * BKC);
            asm volatile("cp.async.commit_group;");
            asm volatile("cp.async.wait_group 1;");
        } else {
            asm volatile("cp.async.wait_group 0;");
        }
        __syncthreads();

        const uint32_t st = sb + (ck & 1) * STAGE_B;
        const uint32_t sAh = st + 0 * TILE_B + aRowOff;
        const uint32_t sAl = st + 1 * TILE_B + aRowOff;
        const uint32_t sBh = st + 2 * TILE_B + bRowOff;
        const uint32_t sBl = st + 3 * TILE_B + bRowOff;

        #pragma unroll
        for (int ks = 0; ks < 2; ++ks) {
            const uint32_t kb = ks * 32;
            uint32_t ah[4][4], al[4][4];
            #pragma unroll
            for (int mt = 0; mt < 4; ++mt) {
                LDSM4(ah[mt][0], ah[mt][1], ah[mt][2], ah[mt][3],
                      sAh + mt * 16 * APITCH + kb);
                LDSM4(al[mt][0], al[mt][1], al[mt][2], al[mt][3],
                      sAl + mt * 16 * APITCH + kb);
            }
            #pragma unroll
            for (int np = 0; np < 4; ++np) {
                uint32_t bh[4], bl[4];
                LDSM4(bh[0], bh[1], bh[2], bh[3], sBh + np * 16 * APITCH + kb);
                LDSM4(bl[0], bl[1], bl[2], bl[3], sBl + np * 16 * APITCH + kb);
                #pragma unroll
                for (int mt = 0; mt < 4; ++mt) {
                    #pragma unroll
                    for (int j = 0; j < 2; ++j) {
                        const int nt = np * 2 + j;
                        MMA16816(acc[mt][nt], ah[mt], bh[j * 2], bh[j * 2 + 1]);
                        MMA16816(acc[mt][nt], al[mt], bh[j * 2], bh[j * 2 + 1]);
                        MMA16816(acc[mt][nt], ah[mt], bl[j * 2], bl[j * 2 + 1]);
                    }
                }
            }
        }
        __syncthreads();
    }

    // Epilogue: write y[col>>6][m][col&63]
    #pragma unroll
    for (int mt = 0; mt < 4; ++mt) {
        #pragma unroll
        for (int nt = 0; nt < 8; ++nt) {
            const int m   = rowBase + wm + mt * 16 + (lane >> 2);
            const int col = colBase + wn + nt * 8 + (lane & 3) * 2;
            const int b = col >> 6, c = col & 63;
            float* base = g_y + (size_t)b * PLANE + c;
            if (m < NNODE)
                *(float2*)(base + (size_t)m * CIN) =
                    make_float2(acc[mt][nt][0], acc[mt][nt][1]);
            if (m + 8 < NNODE)
                *(float2*)(base + (size_t)(m + 8) * CIN) =
                    make_float2(acc[mt][nt][2], acc[mt][nt][3]);
        }
    }
}

// ---------------------------------------------------------------------------
// Kernel 5: per-node HMMA.  out[b,n,o] = A_n(64x128) @ W_n(128x64) + bias_n.
// ---------------------------------------------------------------------------
#define NPITCH 272                       // 256B payload + 16B pad
#define NSM_AH 0
#define NSM_AL (64 * NPITCH)             // 17408
#define NSM_WH (2 * 64 * NPITCH)         // 34816
#define NSM_WL (3 * 64 * NPITCH)         // 52224
#define NSM_TOT (4 * 64 * NPITCH)        // 69632

__global__ void __launch_bounds__(256, 2)
node_mma_kernel(const float* __restrict__ X,
                const float* __restrict__ E,
                const float* __restrict__ bp,
                float* __restrict__ out)
{
    extern __shared__ char dsmem[];
    const uint32_t sb = smem_u32(dsmem);
    __shared__ float e_sh[DDIM];
    __shared__ float bias_sh[64];

    const int n    = blockIdx.x;
    const int tid  = threadIdx.x;
    const int warp = tid >> 5;
    const int lane = tid & 31;

    if (tid < DDIM) e_sh[tid] = E[n * DDIM + tid];

    // Stage W hi/lo
    {
        const uint4* wh = (const uint4*)(g_Wh + (size_t)n * 8192);
        const uint4* wl = (const uint4*)(g_Wl + (size_t)n * 8192);
        #pragma unroll
        for (int i = 0; i < 4; ++i) {
            int seg = tid + i * 256;         // 0..1023
            int o = seg >> 4, s = seg & 15;
            *(uint4*)(dsmem + NSM_WH + o * NPITCH + s * 16) = wh[seg];
            *(uint4*)(dsmem + NSM_WL + o * NPITCH + s * 16) = wl[seg];
        }
    }

    // Stage A hi/lo: rows b (64), 128 ki = [x row | y row], split to bf16.
    #pragma unroll
    for (int idx = tid; idx < 2048; idx += 256) {
        int b  = idx >> 5;
        int i4 = (idx & 31) * 4;
        float4 vv;
        if (i4 < 64)
            vv = *(const float4*)(X + (size_t)b * PLANE + (size_t)n * CIN + i4);
        else
            vv = *(const float4*)(g_y + (size_t)b * PLANE + (size_t)n * CIN + (i4 - 64));
        __nv_bfloat16 h[4], l[4];
        bf16_split(vv.x, h[0], l[0]);
        bf16_split(vv.y, h[1], l[1]);
        bf16_split(vv.z, h[2], l[2]);
        bf16_split(vv.w, h[3], l[3]);
        *(uint2*)(dsmem + NSM_AH + b * NPITCH + i4 * 2) = *(const uint2*)h;
        *(uint2*)(dsmem + NSM_AL + b * NPITCH + i4 * 2) = *(const uint2*)l;
    }

    __syncthreads();
    if (tid < 64) {
        float s = 0.0f;
        #pragma unroll
        for (int d = 0; d < DDIM; ++d) s += e_sh[d] * bp[d * COUT + tid];
        bias_sh[tid] = s;
    }

    const int wm = (warp & 3) * 16;
    const int wn = (warp >> 2) * 32;

    const uint32_t aOff = sb + NSM_AH
        + (uint32_t)((wm + (lane & 15)) * NPITCH + ((lane >> 4) << 4));
    const uint32_t bOff = sb + NSM_WH
        + (uint32_t)((wn + ((lane >> 4) << 3) + (lane & 7)) * NPITCH
                     + (((lane >> 3) & 1) << 4));

    float acc[4][4];
    #pragma unroll
    for (int j = 0; j < 4; ++j)
        #pragma unroll
        for (int q = 0; q < 4; ++q) acc[j][q] = 0.0f;

    #pragma unroll
    for (int ks = 0; ks < 8; ++ks) {
        const uint32_t kb = ks * 32;
        uint32_t ah[4], al[4];
        LDSM4(ah[0], ah[1], ah[2], ah[3], aOff + kb);
        LDSM4(al[0], al[1], al[2], al[3], aOff + (NSM_AL - NSM_AH) + kb);
        #pragma unroll
        for (int np = 0; np < 2; ++np) {
            uint32_t bh[4], bl[4];
            LDSM4(bh[0], bh[1], bh[2], bh[3], bOff + np * 16 * NPITCH + kb);
            LDSM4(bl[0], bl[1], bl[2], bl[3],
                  bOff + (NSM_WL - NSM_WH) + np * 16 * NPITCH + kb);
            #pragma unroll
            for (int j = 0; j < 2; ++j) {
                const int nt = np * 2 + j;
                MMA16816(acc[nt], ah, bh[j * 2], bh[j * 2 + 1]);
                MMA16816(acc[nt], al, bh[j * 2], bh[j * 2 + 1]);
                MMA16816(acc[nt], ah, bl[j * 2], bl[j * 2 + 1]);
            }
        }
    }

    __syncthreads();

    #pragma unroll
    for (int nt = 0; nt < 4; ++nt) {
        const int m   = wm + (lane >> 2);
        const int col = wn + nt * 8 + (lane & 3) * 2;
        const float b0 = bias_sh[col], b1 = bias_sh[col + 1];
        float* base = out + (size_t)n * COUT + col;
        *(float2*)(base + (size_t)m * PLANE) =
            make_float2(acc[nt][0] + b0, acc[nt][1] + b1);
        *(float2*)(base + (size_t)(m + 8) * PLANE) =
            make_float2(acc[nt][2] + b0, acc[nt][3] + b1);
    }
}

// ---------------------------------------------------------------------------
extern "C" void kernel_launch(void* const* d_in, const int* in_sizes, int n_in,
                              void* d_out, int out_size)
{
    const float* x  = (const float*)d_in[0];   // (64, 5000, 64)
    const float* E  = (const float*)d_in[1];   // (5000, 10)
    const float* wp = (const float*)d_in[2];   // (10, 2, 64, 64)
    const float* bp = (const float*)d_in[3];   // (10, 64)
    float* out = (float*)d_out;                // (64, 5000, 64)

    // 1) softmax(relu(E E^T)) rows -> bf16 hi/lo (padded)
    support_split_kernel<<<MPAD, 256>>>(E);

    // 2) transpose x -> B^T hi/lo (K-major, padded)
    dim3 gB(NCOLS / 32, KPAD / 32);
    convert_b_kernel<<<gB, dim3(32, 8)>>>(x);

    // 3) per-node weights W_T (bf16 hi/lo)
    dim3 gW(NNODE / 8, 8);
    wbuild_kernel<<<gW, 256>>>(E, wp);

    // 4) tensor-core GEMM (HMMA): y = support @ x
    cudaFuncSetAttribute(gemm_kernel,
                         cudaFuncAttributeMaxDynamicSharedMemorySize, GEMM_SMEM);
    dim3 gG(NCOLS / BN, MPAD / BM);
    gemm_kernel<<<gG, 128, GEMM_SMEM>>>();

    // 5) per-node HMMA contraction + bias
    cudaFuncSetAttribute(node_mma_kernel,
                         cudaFuncAttributeMaxDynamicSharedMemorySize, NSM_TOT);
    node_mma_kernel<<<NNODE, 256, NSM_TOT>>>(x, E, bp, out);
}